// round 5
// baseline (speedup 1.0000x reference)
#include <cuda_runtime.h>

#define TT 1024

// Inter-layer activations (device globals: allowed scratch)
__device__ float g_h1[256u * 1024u * 32u];        // layer1 output  (33.5 MB)
__device__ float g_h2[256u * 1024u * 64u];        // layer2 output  (67 MB)
__device__ float g_xg3[(size_t)256 * 1024 * 512]; // layer3 input projection (512 MB)

typedef unsigned long long u64;

// ---------------- packed f32x2 helpers ----------------
__device__ __forceinline__ u64 ffma2(u64 a, u64 b, u64 c) {
    u64 d;
    asm("fma.rn.f32x2 %0, %1, %2, %3;" : "=l"(d) : "l"(a), "l"(b), "l"(c));
    return d;
}
__device__ __forceinline__ u64 pack2(float x, float y) {
    u64 r;
    asm("mov.b64 %0, {%1, %2};" : "=l"(r) : "f"(x), "f"(y));
    return r;
}
__device__ __forceinline__ float hsum2(u64 v) {
    float x, y;
    asm("mov.b64 {%0, %1}, %2;" : "=f"(x), "=f"(y) : "l"(v));
    return x + y;
}
__device__ __forceinline__ void unpack2(u64 v, float& x, float& y) {
    asm("mov.b64 {%0, %1}, %2;" : "=f"(x), "=f"(y) : "l"(v));
}
// ---------------- activations (proven: rel_err 4e-7) --------
__device__ __forceinline__ float rcpa(float x) {
    float r; asm("rcp.approx.f32 %0, %1;" : "=f"(r) : "f"(x)); return r;
}
__device__ __forceinline__ float sigf(float x)   { return rcpa(1.f + __expf(-x)); }
__device__ __forceinline__ float tanhf_(float x) { return 1.f - 2.f * rcpa(__expf(2.f * x) + 1.f); }

// ---------------- cluster helpers ----------------
__device__ __forceinline__ unsigned smem_u32(const void* p) {
    return (unsigned)__cvta_generic_to_shared(p);
}
__device__ __forceinline__ unsigned mapa_u32(unsigned a, unsigned r) {
    unsigned o; asm("mapa.shared::cluster.u32 %0, %1, %2;" : "=r"(o) : "r"(a), "r"(r)); return o;
}
__device__ __forceinline__ void st_cluster(unsigned a, float v) {
    asm volatile("st.shared::cluster.f32 [%0], %1;" :: "r"(a), "f"(v) : "memory");
}
__device__ __forceinline__ void cluster_sync_() {
    asm volatile("barrier.cluster.arrive.aligned;" ::: "memory");
    asm volatile("barrier.cluster.wait.aligned;"   ::: "memory");
}
__device__ __forceinline__ unsigned ctarank_() {
    unsigned r; asm("mov.u32 %0, %%cluster_ctarank;" : "=r"(r)); return r;
}
// mbarrier: remote arrive (release.cluster) with count, and cluster-acquire wait
__device__ __forceinline__ void mbar_init_(unsigned a, unsigned cnt) {
    asm volatile("mbarrier.init.shared.b64 [%0], %1;" :: "r"(a), "r"(cnt) : "memory");
}
__device__ __forceinline__ void mbar_arrive_remote_cnt(unsigned remote_a, unsigned cnt) {
    asm volatile("mbarrier.arrive.release.cluster.shared::cluster.b64 _, [%0], %1;"
                 :: "r"(remote_a), "r"(cnt) : "memory");
}
__device__ __forceinline__ void mbar_wait_cluster(unsigned a, unsigned parity) {
    asm volatile(
        "{\n\t.reg .pred P;\n\t"
        "WL_%=:\n\t"
        "mbarrier.try_wait.parity.acquire.cluster.shared::cta.b64 P, [%0], %1, 0x989680;\n\t"
        "@P bra.uni WD_%=;\n\t"
        "bra.uni WL_%=;\n\t"
        "WD_%=:\n\t}"
        :: "r"(a), "r"(parity) : "memory");
}
__device__ __forceinline__ void named_bar_(int id, int cnt) {
    asm volatile("bar.sync %0, %1;" :: "r"(id), "r"(cnt) : "memory");
}

// =======================================================================
// Layer 1: in=1, hid=32.  One WARP per batch element; zero barriers.
// 128 blocks x 64 threads (2 warps = 2 batches) to engage more SMs.
// =======================================================================
__global__ void __launch_bounds__(64, 1) lstm1_kernel(
    const float* __restrict__ x,    const float* __restrict__ w_ih,
    const float* __restrict__ w_hh, const float* __restrict__ b_ih,
    const float* __restrict__ b_hh)
{
    const int tid = threadIdx.x;
    const int j   = tid & 31;
    const int b   = blockIdx.x * 2 + (tid >> 5);

    u64 wif[32], wgo[32];
    #pragma unroll
    for (int k = 0; k < 32; k++) {
        wif[k] = pack2(w_hh[(0  + j) * 32 + k], w_hh[(32 + j) * 32 + k]);
        wgo[k] = pack2(w_hh[(64 + j) * 32 + k], w_hh[(96 + j) * 32 + k]);
    }
    const u64 bif  = pack2(b_ih[j]      + b_hh[j],      b_ih[32 + j] + b_hh[32 + j]);
    const u64 bgo  = pack2(b_ih[64 + j] + b_hh[64 + j], b_ih[96 + j] + b_hh[96 + j]);
    const u64 wiif = pack2(w_ih[j],      w_ih[32 + j]);
    const u64 wigo = pack2(w_ih[64 + j], w_ih[96 + j]);

    const float* __restrict__ xp = x + (size_t)b * TT;
    float* __restrict__ op = g_h1 + (size_t)b * TT * 32 + j;
    float h = 0.f, c = 0.f;
    float xt = xp[0];

    for (int t = 0; t < TT; t++) {
        float xn = (t + 1 < TT) ? xp[t + 1] : 0.f;
        u64 xtp = pack2(xt, xt);
        u64 aif = ffma2(wiif, xtp, bif);
        u64 ago = ffma2(wigo, xtp, bgo);
        #pragma unroll
        for (int k = 0; k < 32; k++) {
            float hk = __shfl_sync(0xffffffffu, h, k);
            u64 hkp = pack2(hk, hk);
            aif = ffma2(wif[k], hkp, aif);
            ago = ffma2(wgo[k], hkp, ago);
        }
        float gi, gf, gg, go;
        unpack2(aif, gi, gf);
        unpack2(ago, gg, go);
        c = sigf(gf) * c + sigf(gi) * tanhf_(gg);
        h = sigf(go) * tanhf_(c);
        op[(size_t)t * 32] = h;
        xt = xn;
    }
}

// =======================================================================
// Layer 2: in=32, hid=64.  128 blocks x 256 threads, 2 batch elems / block.
// (unchanged from passing round)
// =======================================================================
__global__ void __launch_bounds__(256, 1) lstm2_kernel(
    const float* __restrict__ w_ih, const float* __restrict__ w_hh,
    const float* __restrict__ b_ih, const float* __restrict__ b_hh)
{
    __shared__ __align__(16) float h_sm[2][2][64];
    __shared__ __align__(16) float x_sm[2][2][32];
    __shared__ float g_sm[2][4][64];
    const int tid = threadIdx.x;
    const int b0  = blockIdx.x * 2;
    const int gate = tid >> 6, j = tid & 63;

    u64 wh[32], wi[16];
    {
        const ulonglong2* wr = (const ulonglong2*)(w_hh + (size_t)tid * 64);
        #pragma unroll
        for (int q = 0; q < 16; q++) { ulonglong2 v = wr[q]; wh[2*q] = v.x; wh[2*q+1] = v.y; }
        const ulonglong2* wr2 = (const ulonglong2*)(w_ih + (size_t)tid * 32);
        #pragma unroll
        for (int q = 0; q < 8; q++)  { ulonglong2 v = wr2[q]; wi[2*q] = v.x; wi[2*q+1] = v.y; }
    }
    const float bs = b_ih[tid] + b_hh[tid];

    if (tid < 128) h_sm[0][tid >> 6][tid & 63] = 0.f;
    if (tid < 64)  x_sm[0][tid >> 5][tid & 31] =
        g_h1[(size_t)(b0 + (tid >> 5)) * TT * 32 + (tid & 31)];
    float c = 0.f;
    __syncthreads();

    for (int t = 0; t < TT; t++) {
        const int p = t & 1, np = p ^ 1;
        float xn = 0.f;
        if (tid < 64 && t + 1 < TT)
            xn = g_h1[(size_t)(b0 + (tid >> 5)) * TT * 32 + (size_t)(t + 1) * 32 + (tid & 31)];

        u64 a0 = pack2(bs, 0.f), a1 = a0;
        {
            const ulonglong2* xv = (const ulonglong2*)&x_sm[p][0][0];
            #pragma unroll
            for (int q = 0; q < 8; q++) {
                ulonglong2 v0 = xv[q], v1 = xv[8 + q];
                a0 = ffma2(wi[2*q], v0.x, a0); a0 = ffma2(wi[2*q+1], v0.y, a0);
                a1 = ffma2(wi[2*q], v1.x, a1); a1 = ffma2(wi[2*q+1], v1.y, a1);
            }
            const ulonglong2* hv = (const ulonglong2*)&h_sm[p][0][0];
            #pragma unroll
            for (int q = 0; q < 16; q++) {
                ulonglong2 v0 = hv[q], v1 = hv[16 + q];
                a0 = ffma2(wh[2*q], v0.x, a0); a0 = ffma2(wh[2*q+1], v0.y, a0);
                a1 = ffma2(wh[2*q], v1.x, a1); a1 = ffma2(wh[2*q+1], v1.y, a1);
            }
        }
        g_sm[0][gate][j] = hsum2(a0);
        g_sm[1][gate][j] = hsum2(a1);
        __syncthreads();
        if (tid < 128) {
            const int ub = tid >> 6, uj = tid & 63;
            float gi = g_sm[ub][0][uj], gf = g_sm[ub][1][uj];
            float gg = g_sm[ub][2][uj], go = g_sm[ub][3][uj];
            c = sigf(gf) * c + sigf(gi) * tanhf_(gg);
            float h = sigf(go) * tanhf_(c);
            h_sm[np][ub][uj] = h;
            g_h2[(size_t)(b0 + ub) * TT * 64 + (size_t)t * 64 + uj] = h;
        }
        if (tid < 64) x_sm[np][tid >> 5][tid & 31] = xn;
        __syncthreads();
    }
}

// =======================================================================
// xg3 GEMM (unchanged)
// =======================================================================
__global__ void __launch_bounds__(256, 1) xg3_kernel(const float* __restrict__ w_ih)
{
    __shared__ __align__(16) float x_sm[64][64];
    const int tid = threadIdx.x;
    const int b   = blockIdx.y;
    const int t0  = blockIdx.x * 64;

    u64 wa[32], wb[32];
    {
        const ulonglong2* wr = (const ulonglong2*)(w_ih + (size_t)tid * 64);
        #pragma unroll
        for (int q = 0; q < 16; q++) { ulonglong2 v = wr[q]; wa[2*q] = v.x; wa[2*q+1] = v.y; }
        const ulonglong2* wr2 = (const ulonglong2*)(w_ih + (size_t)(tid + 256) * 64);
        #pragma unroll
        for (int q = 0; q < 16; q++) { ulonglong2 v = wr2[q]; wb[2*q] = v.x; wb[2*q+1] = v.y; }
    }
    {
        const float4* src = (const float4*)(g_h2 + (size_t)b * TT * 64 + (size_t)t0 * 64);
        float4* dst = (float4*)&x_sm[0][0];
        #pragma unroll
        for (int i = 0; i < 4; i++) dst[tid + 256 * i] = src[tid + 256 * i];
    }
    __syncthreads();

    float* outp = g_xg3 + ((size_t)b * TT + t0) * 512 + tid;
    for (int tk = 0; tk < 64; tk++) {
        const ulonglong2* xv = (const ulonglong2*)&x_sm[tk][0];
        u64 a0 = pack2(0.f, 0.f), a1 = a0;
        #pragma unroll
        for (int q = 0; q < 16; q++) {
            ulonglong2 v = xv[q];
            a0 = ffma2(wa[2*q], v.x, a0); a0 = ffma2(wa[2*q+1], v.y, a0);
            a1 = ffma2(wb[2*q], v.x, a1); a1 = ffma2(wb[2*q+1], v.y, a1);
        }
        outp[(size_t)tk * 512]       = hsum2(a0);
        outp[(size_t)tk * 512 + 256] = hsum2(a1);
    }
}

// =======================================================================
// Layer 3 v3: mbarrier handshake, role-split halves.
// 64 clusters x 2 CTAs, 4 batches/cluster, 512 threads/CTA.
// Warps with half==rank are updaters: consume locally-produced h (named bar),
// never wait on the cluster. Peer-half warps wait on an mbarrier armed by the
// peer's updater warps (elected arrive.release.cluster, count 32).
// =======================================================================
__global__ void __launch_bounds__(512, 1) __cluster_dims__(2, 1, 1) lstm3_kernel(
    const float* __restrict__ w_hh,
    const float* __restrict__ b_ih, const float* __restrict__ b_hh,
    const float* __restrict__ fc_w, const float* __restrict__ fc_b,
    float* __restrict__ out)
{
    __shared__ __align__(16) float h_sm[2][4][128];    // 4 KB, double-buffered
    __shared__ __align__(16) u64 psum[4][256][2];      // [batch][slot][half] 16 KB
    __shared__ __align__(8)  unsigned long long mbar[1];
    const int tid  = threadIdx.x;
    const unsigned rank = ctarank_();
    const int bg0  = (blockIdx.x >> 1) * 4;
    const int half = tid >> 8;                 // warp-uniform K-half
    const int slot = tid & 255;
    const int gate = slot >> 6, jl = slot & 63;
    const int grow = gate * 128 + (int)rank * 64 + jl; // output gate row (local units)

    u64 wh[32];
    {
        const ulonglong2* wr = (const ulonglong2*)(w_hh + (size_t)grow * 128 + half * 64);
        #pragma unroll
        for (int q = 0; q < 16; q++) { ulonglong2 v = wr[q]; wh[2*q] = v.x; wh[2*q+1] = v.y; }
    }

    const bool upd = (half == (int)rank);      // updater warps consume local h
    const int ub = (slot >> 6), uj = slot & 63;
    float bs0 = 0.f, bs1 = 0.f, bs2 = 0.f, bs3 = 0.f;
    if (upd) {
        const int u = (int)rank * 64 + uj;
        bs0 = b_ih[u]       + b_hh[u];
        bs1 = b_ih[128 + u] + b_hh[128 + u];
        bs2 = b_ih[256 + u] + b_hh[256 + u];
        bs3 = b_ih[384 + u] + b_hh[384 + u];
    }
    const float* __restrict__ xgp =
        g_xg3 + ((size_t)(bg0 + ub) * TT) * 512 + (size_t)rank * 64 + uj;

    unsigned la0 = smem_u32(&h_sm[0][ub][(int)rank * 64 + uj]);
    unsigned la1 = smem_u32(&h_sm[1][ub][(int)rank * 64 + uj]);
    unsigned pa0 = mapa_u32(la0, rank ^ 1u);
    unsigned pa1 = mapa_u32(la1, rank ^ 1u);
    unsigned mb_local = smem_u32(&mbar[0]);
    unsigned mb_peer  = mapa_u32(mb_local, rank ^ 1u);

    if (tid == 0) mbar_init_(mb_local, 256);
    for (int i = tid; i < 2 * 4 * 128; i += 512) ((float*)h_sm)[i] = 0.f;
    __syncthreads();
    cluster_sync_();   // mbar init + h zero visible cluster-wide

    float c = 0.f, hsum = 0.f;
    float x0 = 0.f, x1 = 0.f, x2 = 0.f, x3 = 0.f;
    if (upd) { x0 = xgp[0]; x1 = xgp[128]; x2 = xgp[256]; x3 = xgp[384]; }

    for (int t = 0; t < TT; t++) {
        const int p = t & 1;
        float n0 = 0.f, n1 = 0.f, n2 = 0.f, n3 = 0.f;
        if (upd) {
            if (t + 1 < TT) {
                const size_t o = (size_t)(t + 1) * 512;
                n0 = xgp[o]; n1 = xgp[o + 128]; n2 = xgp[o + 256]; n3 = xgp[o + 384];
            }
        } else {
            if (t) mbar_wait_cluster(mb_local, (t + 1) & 1);  // == (t-1)&1
        }

        u64 a0 = pack2(0.f, 0.f), a1 = a0, a2 = a0, a3 = a0;
        {
            const ulonglong2* hvb = (const ulonglong2*)&h_sm[p][0][0] + half * 16;
            #pragma unroll
            for (int q = 0; q < 16; q++) {
                ulonglong2 v0 = hvb[q], v1 = hvb[32 + q], v2 = hvb[64 + q], v3 = hvb[96 + q];
                a0 = ffma2(wh[2*q], v0.x, a0); a0 = ffma2(wh[2*q+1], v0.y, a0);
                a1 = ffma2(wh[2*q], v1.x, a1); a1 = ffma2(wh[2*q+1], v1.y, a1);
                a2 = ffma2(wh[2*q], v2.x, a2); a2 = ffma2(wh[2*q+1], v2.y, a2);
                a3 = ffma2(wh[2*q], v3.x, a3); a3 = ffma2(wh[2*q+1], v3.y, a3);
            }
        }
        psum[0][slot][half] = a0;
        psum[1][slot][half] = a1;
        psum[2][slot][half] = a2;
        psum[3][slot][half] = a3;
        __syncthreads();   // psum(t) complete

        if (upd) {
            const ulonglong2* ps = (const ulonglong2*)&psum[ub][0][0];
            ulonglong2 q0 = ps[0   + uj], q1 = ps[64  + uj];
            ulonglong2 q2 = ps[128 + uj], q3 = ps[192 + uj];
            float g0 = hsum2(q0.x) + hsum2(q0.y) + bs0 + x0;
            float g1 = hsum2(q1.x) + hsum2(q1.y) + bs1 + x1;
            float g2 = hsum2(q2.x) + hsum2(q2.y) + bs2 + x2;
            float g3 = hsum2(q3.x) + hsum2(q3.y) + bs3 + x3;
            c = sigf(g1) * c + sigf(g0) * tanhf_(g2);
            float h = sigf(g3) * tanhf_(c);
            hsum += h;
            if (p == 0) { h_sm[1][ub][(int)rank * 64 + uj] = h; st_cluster(pa1, h); }
            else        { h_sm[0][ub][(int)rank * 64 + uj] = h; st_cluster(pa0, h); }
            x0 = n0; x1 = n1; x2 = n2; x3 = n3;
            __syncwarp();
            if ((tid & 31) == 0) mbar_arrive_remote_cnt(mb_peer, 32);
            named_bar_(1, 256);   // local h(t+1) visible to updater warps
        }
    }

    // epilogue: pooled mean -> both CTAs' SMEM -> FC on rank 0
    cluster_sync_();
    if (upd) {
        float pv = hsum * (1.f / 1024.f);
        h_sm[0][ub][(int)rank * 64 + uj] = pv;
        st_cluster(pa0, pv);
    }
    cluster_sync_();
    if (rank == 0 && tid < 40) {
        const int b = tid / 10, m = tid % 10;
        float acc = fc_b[m];
        #pragma unroll 8
        for (int jj = 0; jj < 128; jj++)
            acc += h_sm[0][b][jj] * fc_w[m * 128 + jj];
        out[(size_t)(bg0 + b) * 10 + m] = acc;
    }
    cluster_sync_();   // keep peer SMEM alive until FC reads complete
}

// =======================================================================
extern "C" void kernel_launch(void* const* d_in, const int* in_sizes, int n_in,
                              void* d_out, int out_size)
{
    const float* x     = (const float*)d_in[0];
    const float* w_ih1 = (const float*)d_in[1];
    const float* w_hh1 = (const float*)d_in[2];
    const float* b_ih1 = (const float*)d_in[3];
    const float* b_hh1 = (const float*)d_in[4];
    const float* w_ih2 = (const float*)d_in[5];
    const float* w_hh2 = (const float*)d_in[6];
    const float* b_ih2 = (const float*)d_in[7];
    const float* b_hh2 = (const float*)d_in[8];
    const float* w_ih3 = (const float*)d_in[9];
    const float* w_hh3 = (const float*)d_in[10];
    const float* b_ih3 = (const float*)d_in[11];
    const float* b_hh3 = (const float*)d_in[12];
    const float* fc_w  = (const float*)d_in[13];
    const float* fc_b  = (const float*)d_in[14];
    float* out = (float*)d_out;

    lstm1_kernel<<<128, 64>>>(x, w_ih1, w_hh1, b_ih1, b_hh1);
    lstm2_kernel<<<128, 256>>>(w_ih2, w_hh2, b_ih2, b_hh2);
    {
        dim3 grid(TT / 64, 256);
        xg3_kernel<<<grid, 256>>>(w_ih3);
    }
    lstm3_kernel<<<128, 512>>>(w_hh3, b_ih3, b_hh3, fc_w, fc_b, out);
}

// round 6
// speedup vs baseline: 1.0420x; 1.0420x over previous
#include <cuda_runtime.h>

#define TT 1024

// Inter-layer activations (device globals: allowed scratch)
__device__ float g_h1[256u * 1024u * 32u];        // layer1 output  (33.5 MB)
__device__ float g_h2[256u * 1024u * 64u];        // layer2 output  (67 MB)
__device__ float g_xg3[(size_t)256 * 1024 * 512]; // layer3 input projection (512 MB)

typedef unsigned long long u64;

// ---------------- packed f32x2 helpers ----------------
__device__ __forceinline__ u64 ffma2(u64 a, u64 b, u64 c) {
    u64 d;
    asm("fma.rn.f32x2 %0, %1, %2, %3;" : "=l"(d) : "l"(a), "l"(b), "l"(c));
    return d;
}
__device__ __forceinline__ u64 pack2(float x, float y) {
    u64 r;
    asm("mov.b64 %0, {%1, %2};" : "=l"(r) : "f"(x), "f"(y));
    return r;
}
__device__ __forceinline__ float hsum2(u64 v) {
    float x, y;
    asm("mov.b64 {%0, %1}, %2;" : "=f"(x), "=f"(y) : "l"(v));
    return x + y;
}
__device__ __forceinline__ void unpack2(u64 v, float& x, float& y) {
    asm("mov.b64 {%0, %1}, %2;" : "=f"(x), "=f"(y) : "l"(v));
}
// ---------------- activations (proven: rel_err 4e-7) --------
__device__ __forceinline__ float rcpa(float x) {
    float r; asm("rcp.approx.f32 %0, %1;" : "=f"(r) : "f"(x)); return r;
}
__device__ __forceinline__ float sigf(float x)   { return rcpa(1.f + __expf(-x)); }
__device__ __forceinline__ float tanhf_(float x) { return 1.f - 2.f * rcpa(__expf(2.f * x) + 1.f); }

// ---------------- cluster helpers ----------------
__device__ __forceinline__ unsigned smem_u32(const void* p) {
    return (unsigned)__cvta_generic_to_shared(p);
}
__device__ __forceinline__ unsigned mapa_u32(unsigned a, unsigned r) {
    unsigned o; asm("mapa.shared::cluster.u32 %0, %1, %2;" : "=r"(o) : "r"(a), "r"(r)); return o;
}
__device__ __forceinline__ void st_cluster(unsigned a, float v) {
    asm volatile("st.shared::cluster.f32 [%0], %1;" :: "r"(a), "f"(v) : "memory");
}
__device__ __forceinline__ void cluster_sync_() {
    asm volatile("barrier.cluster.arrive.aligned;" ::: "memory");
    asm volatile("barrier.cluster.wait.aligned;"   ::: "memory");
}
__device__ __forceinline__ unsigned ctarank_() {
    unsigned r; asm("mov.u32 %0, %%cluster_ctarank;" : "=r"(r)); return r;
}

// =======================================================================
// Layer 1: in=1, hid=32.  One WARP per batch element; zero barriers.
// 128 blocks x 64 threads (2 warps = 2 batches).
// =======================================================================
__global__ void __launch_bounds__(64, 1) lstm1_kernel(
    const float* __restrict__ x,    const float* __restrict__ w_ih,
    const float* __restrict__ w_hh, const float* __restrict__ b_ih,
    const float* __restrict__ b_hh)
{
    const int tid = threadIdx.x;
    const int j   = tid & 31;
    const int b   = blockIdx.x * 2 + (tid >> 5);

    u64 wif[32], wgo[32];
    #pragma unroll
    for (int k = 0; k < 32; k++) {
        wif[k] = pack2(w_hh[(0  + j) * 32 + k], w_hh[(32 + j) * 32 + k]);
        wgo[k] = pack2(w_hh[(64 + j) * 32 + k], w_hh[(96 + j) * 32 + k]);
    }
    const u64 bif  = pack2(b_ih[j]      + b_hh[j],      b_ih[32 + j] + b_hh[32 + j]);
    const u64 bgo  = pack2(b_ih[64 + j] + b_hh[64 + j], b_ih[96 + j] + b_hh[96 + j]);
    const u64 wiif = pack2(w_ih[j],      w_ih[32 + j]);
    const u64 wigo = pack2(w_ih[64 + j], w_ih[96 + j]);

    const float* __restrict__ xp = x + (size_t)b * TT;
    float* __restrict__ op = g_h1 + (size_t)b * TT * 32 + j;
    float h = 0.f, c = 0.f;
    float xt = xp[0];

    for (int t = 0; t < TT; t++) {
        float xn = (t + 1 < TT) ? xp[t + 1] : 0.f;
        u64 xtp = pack2(xt, xt);
        u64 aif = ffma2(wiif, xtp, bif);
        u64 ago = ffma2(wigo, xtp, bgo);
        #pragma unroll
        for (int k = 0; k < 32; k++) {
            float hk = __shfl_sync(0xffffffffu, h, k);
            u64 hkp = pack2(hk, hk);
            aif = ffma2(wif[k], hkp, aif);
            ago = ffma2(wgo[k], hkp, ago);
        }
        float gi, gf, gg, go;
        unpack2(aif, gi, gf);
        unpack2(ago, gg, go);
        c = sigf(gf) * c + sigf(gi) * tanhf_(gg);
        h = sigf(go) * tanhf_(c);
        op[(size_t)t * 32] = h;
        xt = xn;
    }
}

// =======================================================================
// Layer 2 v2: in=32, hid=64.  ONE batch per CTA, 256 CTAs x 256 threads,
// 2 CTAs/SM (independent batches overlap barrier stalls).
// Thread r owns gate-row r: 64 w_hh + 32 w_ih weights in regs (~96).
// =======================================================================
__global__ void __launch_bounds__(256, 2) lstm2_kernel(
    const float* __restrict__ w_ih, const float* __restrict__ w_hh,
    const float* __restrict__ b_ih, const float* __restrict__ b_hh)
{
    __shared__ __align__(16) float h_sm[2][64];
    __shared__ __align__(16) float x_sm[2][32];
    __shared__ float g_sm[256];
    const int tid = threadIdx.x;
    const int b   = blockIdx.x;

    u64 wh[32], wi[16];
    {
        const ulonglong2* wr = (const ulonglong2*)(w_hh + (size_t)tid * 64);
        #pragma unroll
        for (int q = 0; q < 16; q++) { ulonglong2 v = wr[q]; wh[2*q] = v.x; wh[2*q+1] = v.y; }
        const ulonglong2* wr2 = (const ulonglong2*)(w_ih + (size_t)tid * 32);
        #pragma unroll
        for (int q = 0; q < 8; q++)  { ulonglong2 v = wr2[q]; wi[2*q] = v.x; wi[2*q+1] = v.y; }
    }
    const float bs = b_ih[tid] + b_hh[tid];
    const float* __restrict__ xin = g_h1 + (size_t)b * TT * 32;
    float* __restrict__ op = g_h2 + (size_t)b * TT * 64;

    if (tid < 64) h_sm[0][tid] = 0.f;
    if (tid < 32) x_sm[0][tid] = xin[tid];
    float c = 0.f;
    __syncthreads();

    for (int t = 0; t < TT; t++) {
        const int p = t & 1, np = p ^ 1;
        float xn = 0.f;
        if (tid < 32 && t + 1 < TT) xn = xin[(size_t)(t + 1) * 32 + tid];

        u64 a = pack2(bs, 0.f);
        {
            const ulonglong2* xv = (const ulonglong2*)&x_sm[p][0];
            #pragma unroll
            for (int q = 0; q < 8; q++) {
                ulonglong2 v = xv[q];
                a = ffma2(wi[2*q], v.x, a); a = ffma2(wi[2*q+1], v.y, a);
            }
            const ulonglong2* hv = (const ulonglong2*)&h_sm[p][0];
            #pragma unroll
            for (int q = 0; q < 16; q++) {
                ulonglong2 v = hv[q];
                a = ffma2(wh[2*q], v.x, a); a = ffma2(wh[2*q+1], v.y, a);
            }
        }
        g_sm[tid] = hsum2(a);
        __syncthreads();
        if (tid < 64) {
            float gi = g_sm[tid],       gf = g_sm[64 + tid];
            float gg = g_sm[128 + tid], go = g_sm[192 + tid];
            c = sigf(gf) * c + sigf(gi) * tanhf_(gg);
            float h = sigf(go) * tanhf_(c);
            h_sm[np][tid] = h;
            op[(size_t)t * 64 + tid] = h;
        }
        if (tid < 32) x_sm[np][tid] = xn;
        __syncthreads();
    }
}

// =======================================================================
// xg3 GEMM (unchanged)
// =======================================================================
__global__ void __launch_bounds__(256, 1) xg3_kernel(const float* __restrict__ w_ih)
{
    __shared__ __align__(16) float x_sm[64][64];
    const int tid = threadIdx.x;
    const int b   = blockIdx.y;
    const int t0  = blockIdx.x * 64;

    u64 wa[32], wb[32];
    {
        const ulonglong2* wr = (const ulonglong2*)(w_ih + (size_t)tid * 64);
        #pragma unroll
        for (int q = 0; q < 16; q++) { ulonglong2 v = wr[q]; wa[2*q] = v.x; wa[2*q+1] = v.y; }
        const ulonglong2* wr2 = (const ulonglong2*)(w_ih + (size_t)(tid + 256) * 64);
        #pragma unroll
        for (int q = 0; q < 16; q++) { ulonglong2 v = wr2[q]; wb[2*q] = v.x; wb[2*q+1] = v.y; }
    }
    {
        const float4* src = (const float4*)(g_h2 + (size_t)b * TT * 64 + (size_t)t0 * 64);
        float4* dst = (float4*)&x_sm[0][0];
        #pragma unroll
        for (int i = 0; i < 4; i++) dst[tid + 256 * i] = src[tid + 256 * i];
    }
    __syncthreads();

    float* outp = g_xg3 + ((size_t)b * TT + t0) * 512 + tid;
    for (int tk = 0; tk < 64; tk++) {
        const ulonglong2* xv = (const ulonglong2*)&x_sm[tk][0];
        u64 a0 = pack2(0.f, 0.f), a1 = a0;
        #pragma unroll
        for (int q = 0; q < 16; q++) {
            ulonglong2 v = xv[q];
            a0 = ffma2(wa[2*q], v.x, a0); a0 = ffma2(wa[2*q+1], v.y, a0);
            a1 = ffma2(wb[2*q], v.x, a1); a1 = ffma2(wb[2*q+1], v.y, a1);
        }
        outp[(size_t)tk * 512]       = hsum2(a0);
        outp[(size_t)tk * 512 + 256] = hsum2(a1);
    }
}

// =======================================================================
// Layer 3 v4: in=64, hid=128.  64 clusters x 4 CTAs, 4 batches/cluster,
// 256 threads/CTA, 2 CTAs/SM (co-residents come from different clusters ->
// independent barrier domains overlap stalls).
// CTA rank owns units [rank*32, rank*32+32) -> 128 gate rows; thread owns
// (row, K-half): 32 packed u64 weights. Updater (tid<128) combines psum
// halves, folds bias+xg3, activations, broadcasts its 32 units' h to all
// 3 peer CTAs via DSMEM. Plain barrier.cluster per step (proven).
// =======================================================================
__global__ void __launch_bounds__(256, 2) __cluster_dims__(4, 1, 1) lstm3_kernel(
    const float* __restrict__ w_hh,
    const float* __restrict__ b_ih, const float* __restrict__ b_hh,
    const float* __restrict__ fc_w, const float* __restrict__ fc_b,
    float* __restrict__ out)
{
    __shared__ __align__(16) float h_sm[2][4][128];   // 4 KB, double-buffered, ALL 128 units
    __shared__ __align__(16) u64 psum[2][4][128];     // [half][batch][slot] 8 KB
    const int tid  = threadIdx.x;
    const unsigned rank = ctarank_();
    const int bg0  = (blockIdx.x >> 2) * 4;
    const int half = tid >> 7;                 // K-half (warp-uniform)
    const int slot = tid & 127;
    const int gate = slot >> 5, jl = slot & 31;
    const int grow = gate * 128 + (int)rank * 32 + jl;  // global gate row

    u64 wh[32];
    {
        const ulonglong2* wr = (const ulonglong2*)(w_hh + (size_t)grow * 128 + half * 64);
        #pragma unroll
        for (int q = 0; q < 16; q++) { ulonglong2 v = wr[q]; wh[2*q] = v.x; wh[2*q+1] = v.y; }
    }

    const bool upd = (tid < 128);
    const int ub = tid >> 5, uj = tid & 31;    // updater: batch ub, local unit uj
    const int u  = (int)rank * 32 + uj;        // global unit
    float bs0 = 0.f, bs1 = 0.f, bs2 = 0.f, bs3 = 0.f;
    if (upd) {
        bs0 = b_ih[u]       + b_hh[u];
        bs1 = b_ih[128 + u] + b_hh[128 + u];
        bs2 = b_ih[256 + u] + b_hh[256 + u];
        bs3 = b_ih[384 + u] + b_hh[384 + u];
    }
    const float* __restrict__ xgp =
        g_xg3 + ((size_t)(bg0 + (upd ? ub : 0)) * TT) * 512 + u;

    // remote h addresses: 3 peers x 2 buffers
    unsigned la0 = smem_u32(&h_sm[0][ub & 3][u]);
    unsigned la1 = smem_u32(&h_sm[1][ub & 3][u]);
    unsigned p0a = 0, p0b = 0, p1a = 0, p1b = 0, p2a = 0, p2b = 0;
    {
        unsigned r0 = (rank + 1) & 3, r1 = (rank + 2) & 3, r2 = (rank + 3) & 3;
        p0a = mapa_u32(la0, r0); p0b = mapa_u32(la1, r0);
        p1a = mapa_u32(la0, r1); p1b = mapa_u32(la1, r1);
        p2a = mapa_u32(la0, r2); p2b = mapa_u32(la1, r2);
    }

    for (int i = tid; i < 2 * 4 * 128; i += 256) ((float*)h_sm)[i] = 0.f;
    __syncthreads();
    cluster_sync_();   // zeroed h visible cluster-wide

    float c = 0.f, hsum = 0.f;
    float x0 = 0.f, x1 = 0.f, x2 = 0.f, x3 = 0.f;
    if (upd) { x0 = xgp[0]; x1 = xgp[128]; x2 = xgp[256]; x3 = xgp[384]; }

    for (int t = 0; t < TT; t++) {
        const int p = t & 1;
        float n0 = 0.f, n1 = 0.f, n2 = 0.f, n3 = 0.f;
        if (upd && t + 1 < TT) {
            const size_t o = (size_t)(t + 1) * 512;
            n0 = xgp[o]; n1 = xgp[o + 128]; n2 = xgp[o + 256]; n3 = xgp[o + 384];
        }

        u64 a0 = pack2(0.f, 0.f), a1 = a0, a2 = a0, a3 = a0;
        {
            const ulonglong2* hvb = (const ulonglong2*)&h_sm[p][0][0] + half * 16;
            #pragma unroll
            for (int q = 0; q < 16; q++) {
                ulonglong2 v0 = hvb[q], v1 = hvb[32 + q], v2 = hvb[64 + q], v3 = hvb[96 + q];
                a0 = ffma2(wh[2*q], v0.x, a0); a0 = ffma2(wh[2*q+1], v0.y, a0);
                a1 = ffma2(wh[2*q], v1.x, a1); a1 = ffma2(wh[2*q+1], v1.y, a1);
                a2 = ffma2(wh[2*q], v2.x, a2); a2 = ffma2(wh[2*q+1], v2.y, a2);
                a3 = ffma2(wh[2*q], v3.x, a3); a3 = ffma2(wh[2*q+1], v3.y, a3);
            }
        }
        psum[half][0][slot] = a0;
        psum[half][1][slot] = a1;
        psum[half][2][slot] = a2;
        psum[half][3][slot] = a3;
        __syncthreads();   // psum(t) complete

        if (upd) {
            float g0 = hsum2(psum[0][ub][uj])      + hsum2(psum[1][ub][uj])      + bs0 + x0;
            float g1 = hsum2(psum[0][ub][32 + uj]) + hsum2(psum[1][ub][32 + uj]) + bs1 + x1;
            float g2 = hsum2(psum[0][ub][64 + uj]) + hsum2(psum[1][ub][64 + uj]) + bs2 + x2;
            float g3 = hsum2(psum[0][ub][96 + uj]) + hsum2(psum[1][ub][96 + uj]) + bs3 + x3;
            c = sigf(g1) * c + sigf(g0) * tanhf_(g2);
            float h = sigf(g3) * tanhf_(c);
            hsum += h;
            if (p == 0) {
                h_sm[1][ub][u] = h;
                st_cluster(p0b, h); st_cluster(p1b, h); st_cluster(p2b, h);
            } else {
                h_sm[0][ub][u] = h;
                st_cluster(p0a, h); st_cluster(p1a, h); st_cluster(p2a, h);
            }
            x0 = n0; x1 = n1; x2 = n2; x3 = n3;
        }
        cluster_sync_();
    }

    // epilogue: pooled mean -> rank 0's h_sm[0] -> FC on rank 0
    if (upd) {
        float pv = hsum * (1.f / 1024.f);
        if (rank == 0) h_sm[0][ub][u] = pv;
        else           st_cluster(mapa_u32(la0, 0u), pv);
    }
    cluster_sync_();
    if (rank == 0 && tid < 40) {
        const int b = tid / 10, m = tid % 10;
        float acc = fc_b[m];
        #pragma unroll 8
        for (int jj = 0; jj < 128; jj++)
            acc += h_sm[0][b][jj] * fc_w[m * 128 + jj];
        out[(size_t)(bg0 + b) * 10 + m] = acc;
    }
    cluster_sync_();   // keep SMEM alive until FC reads complete
}

// =======================================================================
extern "C" void kernel_launch(void* const* d_in, const int* in_sizes, int n_in,
                              void* d_out, int out_size)
{
    const float* x     = (const float*)d_in[0];
    const float* w_ih1 = (const float*)d_in[1];
    const float* w_hh1 = (const float*)d_in[2];
    const float* b_ih1 = (const float*)d_in[3];
    const float* b_hh1 = (const float*)d_in[4];
    const float* w_ih2 = (const float*)d_in[5];
    const float* w_hh2 = (const float*)d_in[6];
    const float* b_ih2 = (const float*)d_in[7];
    const float* b_hh2 = (const float*)d_in[8];
    const float* w_ih3 = (const float*)d_in[9];
    const float* w_hh3 = (const float*)d_in[10];
    const float* b_ih3 = (const float*)d_in[11];
    const float* b_hh3 = (const float*)d_in[12];
    const float* fc_w  = (const float*)d_in[13];
    const float* fc_b  = (const float*)d_in[14];
    float* out = (float*)d_out;

    lstm1_kernel<<<128, 64>>>(x, w_ih1, w_hh1, b_ih1, b_hh1);
    lstm2_kernel<<<256, 256>>>(w_ih2, w_hh2, b_ih2, b_hh2);
    {
        dim3 grid(TT / 64, 256);
        xg3_kernel<<<grid, 256>>>(w_ih3);
    }
    lstm3_kernel<<<256, 256>>>(w_hh3, b_ih3, b_hh3, fc_w, fc_b, out);
}